// round 10
// baseline (speedup 1.0000x reference)
#include <cuda_runtime.h>
#include <float.h>

#define Tn   2048
#define Bn   512
#define INn  27
#define Hn   64
#define OUTn 26
#define Gn   256   // 4*H
#define BPC  4     // batches per CTA in stage 1

// scratch: h history (256 MB) + input-gate preactivations, batch-pair
// interleaved: g_xw2[(t*(Bn/2) + bpair)*Gn + g'] = {pre[2*bpair], pre[2*bpair+1]}
__device__ float  g_hall[Tn * Bn * Hn];
__device__ float2 g_xw2[(size_t)Tn * (Bn / 2) * Gn];

// ---- packed f32x2 helpers (Blackwell FFMA2) ----
__device__ __forceinline__ unsigned long long pack2(float lo, float hi) {
    unsigned long long r;
    asm("mov.b64 %0, {%1, %2};" : "=l"(r) : "f"(lo), "f"(hi));
    return r;
}
__device__ __forceinline__ void unpack2(unsigned long long v, float& lo, float& hi) {
    asm("mov.b64 {%0, %1}, %2;" : "=f"(lo), "=f"(hi) : "l"(v));
}
__device__ __forceinline__ unsigned long long ffma2(unsigned long long a,
                                                    unsigned long long b,
                                                    unsigned long long c) {
    unsigned long long d;
    asm("fma.rn.f32x2 %0, %1, %2, %3;" : "=l"(d) : "l"(a), "l"(b), "l"(c));
    return d;
}
__device__ __forceinline__ float ex2f(float x) {
    float y; asm("ex2.approx.f32 %0, %1;" : "=f"(y) : "f"(x)); return y;
}
__device__ __forceinline__ float rcpf(float x) {
    float y; asm("rcp.approx.f32 %0, %1;" : "=f"(y) : "f"(x)); return y;
}

// ============================================================================
// Kernel 0: xw2[t][bp][g'] = { x[t,2bp,:].W_ih[g]+b, x[t,2bp+1,:].W_ih[g]+b }
// g' permuted to stage-1 lane order (tid = hg*32 + gt*8 + h7, g = gt*64+hg*8+h7).
// LDS.128 x reads, STG.64 pair stores (R9 was L1-wavefront bound at 87%).
// ============================================================================
__global__ __launch_bounds__(256)
void xw_kernel(const float* __restrict__ x,      // [T,B,IN]
               const float* __restrict__ W_ih,   // [256,27]
               const float* __restrict__ b_ih,
               const float* __restrict__ b_hh)
{
    const int t   = blockIdx.x;
    const int tid = threadIdx.x;
    const int gt  = (tid >> 3) & 3;
    const int hg  = tid >> 5;
    const int h7  = tid & 7;
    const int g   = gt * 64 + hg * 8 + h7;

    unsigned long long wp[28];
    {
        const float* wr = W_ih + g * INn;
#pragma unroll
        for (int k = 0; k < 27; k++) { float w = wr[k]; wp[k] = pack2(w, w); }
        wp[27] = 0ull;
    }
    const float bias = b_ih[g] + b_hh[g];
    const unsigned long long bias2 = pack2(bias, bias);

    __shared__ __align__(16) unsigned long long xs[8][28];  // 8 pairs x 28 cols
    if (tid < 8) xs[tid][27] = 0ull;        // pad col, written once

    float2* outb = g_xw2 + (size_t)t * (Bn / 2) * Gn;

    for (int bb = 0; bb < Bn; bb += 16) {
        __syncthreads();
        if (tid < 216) {
            int p = tid / 27, k = tid - p * 27;
            size_t a = ((size_t)t * Bn + bb + 2 * p) * INn + k;
            xs[p][k] = pack2(x[a], x[a + INn]);
        }
        __syncthreads();
#pragma unroll
        for (int p = 0; p < 8; p++) {
            unsigned long long acc = bias2;
            const ulonglong2* xv = (const ulonglong2*)xs[p];
#pragma unroll
            for (int k = 0; k < 14; k++) {
                ulonglong2 u = xv[k];                  // LDS.128 (broadcast)
                acc = ffma2(u.x, wp[2 * k],     acc);
                acc = ffma2(u.y, wp[2 * k + 1], acc);
            }
            float lo, hi; unpack2(acc, lo, hi);
            outb[(size_t)(bb / 2 + p) * Gn + tid] = make_float2(lo, hi);  // STG.64
        }
    }
}

// ============================================================================
// Stage 1: 512 LSTMs, 4 batches/CTA -> grid 128 (single wave), 512 threads.
// Thread = 1 gate x 2 batches; W_hh register-resident; xw via one LDG.64/step.
// Pair 0 (warps 0-7) and pair 1 (warps 8-15) share NO state -> per-pair named
// barriers (bar.sync 1/2) let the halves slide and interleave FFMA/MUFU phases.
// ============================================================================
__global__ __launch_bounds__(512, 1)
void lstm_kernel(const float* __restrict__ W_hh)   // [256,64]
{
    const int tid  = threadIdx.x;
    const int lane = tid & 31;
    const int warp = tid >> 5;
    const int pair = warp >> 3;               // 0 or 1
    const int hg   = warp & 7;
    const int hloc = hg * 8 + (lane & 7);
    const int gtyp = lane >> 3;               // 0:i 1:f 2:g 3:o
    const int g    = gtyp * 64 + hloc;

    const int bl0 = 2 * pair;
    const int bg0 = blockIdx.x * BPC + bl0;
    const int barid = pair + 1;

    __shared__ __align__(16) float h_s[2][BPC][Hn];

    unsigned long long whh[32];
    {
        const float* wr = W_hh + g * Hn;
#pragma unroll
        for (int k = 0; k < 32; k++) whh[k] = pack2(wr[2 * k], wr[2 * k + 1]);
    }

    // act = A * rcp(1 + ex2(K*pre)) + C   (gtyp2: tanh = 2*sigm(2x)-1)
    const float K = (gtyp == 2) ? -2.8853900817779268f : -1.4426950408889634f;
    const float A = (gtyp == 2) ?  2.0f : 1.0f;
    const float C = (gtyp == 2) ? -1.0f : 0.0f;

    float c = 0.0f;

    // xw pointer: one float2 per step (both batches of this pair)
    const float2* xwp = g_xw2
        + (size_t)(blockIdx.x * 2 + pair) * Gn + hg * 32 + lane;
    // h-history pointer (owner lanes 0-15)
    const int bsel = (lane >> 3) & 1;
    float* hallp = g_hall + (size_t)(bg0 + bsel) * Hn + hloc;

    if (tid < BPC * Hn) ((float*)h_s[0])[tid] = 0.0f;

    float2 xr = *xwp;
    xwp += (size_t)(Bn / 2) * Gn;
    __syncthreads();

    int buf = 0;
    for (int t = 0; t < Tn; t++) {
        // prefetch xw for t+1
        float2 nx = make_float2(0.0f, 0.0f);
        if (t + 1 < Tn) nx = *xwp;
        xwp += (size_t)(Bn / 2) * Gn;

        // gate pre-activation: h . W_hh (x-part + biases already in xr)
        unsigned long long a00 = 0ull, a01 = 0ull, a10 = 0ull, a11 = 0ull;
        const ulonglong2* hp0 = (const ulonglong2*)h_s[buf][bl0];
        const ulonglong2* hp1 = (const ulonglong2*)h_s[buf][bl0 + 1];
#pragma unroll
        for (int k = 0; k < 16; k++) {
            ulonglong2 h0 = hp0[k];
            ulonglong2 h1 = hp1[k];
            a00 = ffma2(h0.x, whh[2 * k],     a00);
            a01 = ffma2(h0.y, whh[2 * k + 1], a01);
            a10 = ffma2(h1.x, whh[2 * k],     a10);
            a11 = ffma2(h1.y, whh[2 * k + 1], a11);
        }
        float p0, q0, r0, s0, p1, q1, r1, s1;
        unpack2(a00, p0, q0); unpack2(a01, r0, s0);
        unpack2(a10, p1, q1); unpack2(a11, r1, s1);
        float acc0 = xr.x + ((p0 + q0) + (r0 + s0));
        float acc1 = xr.y + ((p1 + q1) + (r1 + s1));
        xr = nx;

        float act0 = fmaf(A, rcpf(1.0f + ex2f(K * acc0)), C);
        float act1 = fmaf(A, rcpf(1.0f + ex2f(K * acc1)), C);

        // gather i,f,g,o for this lane's (h, batch)
        const int base = lane & 7;
        float i0 = __shfl_sync(0xffffffffu, act0, base);
        float i1 = __shfl_sync(0xffffffffu, act1, base);
        float f0 = __shfl_sync(0xffffffffu, act0, base + 8);
        float f1 = __shfl_sync(0xffffffffu, act1, base + 8);
        float g0 = __shfl_sync(0xffffffffu, act0, base + 16);
        float g1 = __shfl_sync(0xffffffffu, act1, base + 16);
        float o0 = __shfl_sync(0xffffffffu, act0, base + 24);
        float o1 = __shfl_sync(0xffffffffu, act1, base + 24);
        const bool sel = (lane & 8) != 0;
        float iv = sel ? i1 : i0;
        float fv = sel ? f1 : f0;
        float gv = sel ? g1 : g0;
        float ov = sel ? o1 : o0;

        // cell/hidden update: lanes 0-15 own (h = hloc, batch = bl0+bsel)
        c = fmaf(fv, c, iv * gv);
        float th = fmaf(2.0f, rcpf(1.0f + ex2f(-2.8853900817779268f * c)), -1.0f);
        float hv = ov * th;
        if (lane < 16) {
            h_s[buf ^ 1][bl0 + bsel][hloc] = hv;
            *hallp = hv;
        }
        hallp += (size_t)Bn * Hn;
        // per-pair named barrier: warps 0-7 <-> id 1, warps 8-15 <-> id 2
        asm volatile("bar.sync %0, %1;" :: "r"(barid), "r"(256) : "memory");
        buf ^= 1;
    }
}

// ============================================================================
// Stage 2 (unchanged, 70.9us): single-pass BN-stats + masked-extrema + pool
// + FC, one CTA per timestep.
// ============================================================================
__global__ __launch_bounds__(256)
void bn_pool_fc_kernel(const float* __restrict__ pg,     // [T,OUT]
                       const float* __restrict__ gamma,  // [H]
                       const float* __restrict__ beta,   // [H]
                       const float* __restrict__ W_fc,   // [OUT, H+OUT]
                       const float* __restrict__ b_fc,   // [OUT]
                       const float* __restrict__ mask,   // [B,H]
                       float* __restrict__ out)          // [T,1,OUT]
{
    const int t   = blockIdx.x;
    const int tid = threadIdx.x;
    const int h   = tid & 63;
    const int grp = tid >> 6;

    const float* base = g_hall + (size_t)t * Bn * Hn;

    __shared__ float rS[4][Hn], rQ[4][Hn], rMx[4][Hn], rMn[4][Hn],
                     rMv[4][Hn], rZ[4][Hn];
    __shared__ float pooled[Hn];

    float s = 0.0f, ss = 0.0f;
    float vmx = -FLT_MAX, vmn = FLT_MAX, mv = 0.0f, anyz = 0.0f;
#pragma unroll 4
    for (int bb = grp; bb < Bn; bb += 4) {
        float v = base[bb * Hn + h];
        float m = mask[bb * Hn + h];
        s  += v;
        ss += v * v;
        if (m > 0.0f) {
            vmx = fmaxf(vmx, v);
            vmn = fminf(vmn, v);
            mv  = fmaxf(mv, m);
        } else {
            anyz = 1.0f;
        }
    }
    rS[grp][h] = s;    rQ[grp][h] = ss;
    rMx[grp][h] = vmx; rMn[grp][h] = vmn;
    rMv[grp][h] = mv;  rZ[grp][h] = anyz;
    __syncthreads();

    if (tid < Hn) {
        float sum = rS[0][tid] + rS[1][tid] + rS[2][tid] + rS[3][tid];
        float sq  = rQ[0][tid] + rQ[1][tid] + rQ[2][tid] + rQ[3][tid];
        float mx  = fmaxf(fmaxf(rMx[0][tid], rMx[1][tid]),
                          fmaxf(rMx[2][tid], rMx[3][tid]));
        float mn  = fminf(fminf(rMn[0][tid], rMn[1][tid]),
                          fminf(rMn[2][tid], rMn[3][tid]));
        float m   = fmaxf(fmaxf(rMv[0][tid], rMv[1][tid]),
                          fmaxf(rMv[2][tid], rMv[3][tid]));
        float z   = fmaxf(fmaxf(rZ[0][tid], rZ[1][tid]),
                          fmaxf(rZ[2][tid], rZ[3][tid]));
        float mean = sum * (1.0f / Bn);
        float var  = sq * (1.0f / Bn) - mean * mean;
        float rstd = rsqrtf(var + 1e-5f);
        float sc   = rstd * gamma[tid];
        float sh   = beta[tid] - mean * sc;

        float p;
        if (mx == -FLT_MAX) {
            p = 0.0f;
        } else {
            float vstar = (sc >= 0.0f) ? mx : mn;
            p = m * (vstar * sc + sh);
            if (z > 0.0f) p = fmaxf(p, 0.0f);
        }
        pooled[tid] = p;
    }
    __syncthreads();

    if (tid < OUTn) {
        const float* w = W_fc + tid * (Hn + OUTn);
        float acc = b_fc[tid];
#pragma unroll
        for (int k = 0; k < Hn; k++) acc += pooled[k] * w[k];
#pragma unroll
        for (int k = 0; k < OUTn; k++) acc += pg[t * OUTn + k] * w[Hn + k];
        out[t * OUTn + tid] = acc;
    }
}

// ============================================================================
// Launch
// ============================================================================
extern "C" void kernel_launch(void* const* d_in, const int* in_sizes, int n_in,
                              void* d_out, int out_size) {
    const float* x      = (const float*)d_in[0];
    const float* pg     = (const float*)d_in[1];
    const float* W_ih   = (const float*)d_in[2];
    const float* W_hh   = (const float*)d_in[3];
    const float* b_ih   = (const float*)d_in[4];
    const float* b_hh   = (const float*)d_in[5];
    const float* gamma  = (const float*)d_in[6];
    const float* beta   = (const float*)d_in[7];
    const float* W_fc   = (const float*)d_in[8];
    const float* b_fc   = (const float*)d_in[9];
    const float* dmask  = (const float*)d_in[10];
    float* out = (float*)d_out;

    xw_kernel<<<Tn, 256>>>(x, W_ih, b_ih, b_hh);
    lstm_kernel<<<Bn / BPC, 512>>>(W_hh);
    bn_pool_fc_kernel<<<Tn, 256>>>(pg, gamma, beta, W_fc, b_fc, dmask, out);
}